// round 9
// baseline (speedup 1.0000x reference)
#include <cuda_runtime.h>
#include <cuda_bf16.h>
#include <math.h>

// Attention path collapses (softmax rows sum to 1; T,S fully contracted):
//   y = 1024 * (h_pred @ Wv + bv)
// Only Wv/Wo projection + gate MLP + mixer MLP survive.
//
// R8: k-slices live INSIDE the warp (s = lane&3, c = warp*8 + lane>>2), so
// the cross-slice reduce is 2 shfl.xor rounds instead of smem partials +
// barrier. 6 barriers instead of 11; 16KB partial buffer gone; smem 17KB.
// Activation smem uses XOR-pad swizzle (k*8 + (k>>5)*4), conflict-free for
// the 4-address broadcast LDS.128 pattern.

#define HID 128
#define ROWS 8
#define NNODES 1024
#define NTHREADS 512

typedef unsigned long long u64;

// swizzled activation index (float units): conflict-free across 4 k-slices
__device__ __forceinline__ int SW(int k) { return k * 8 + ((k >> 5) << 2); }

#define BUF_A  0      // h_pred, later h_corr
#define BUF_HV 1040   // h_prev
#define BUF_C  2080   // v, later m1
#define BUF_G  3120   // gate hidden, later final staging
#define SMF_TOT 4160

__device__ __forceinline__ u64 fma2(u64 a, u64 b, u64 c) {
    u64 d;
    asm("fma.rn.f32x2 %0, %1, %2, %3;" : "=l"(d) : "l"(a), "l"(b), "l"(c));
    return d;
}

__device__ __forceinline__ void load16(const float* __restrict__ W, int c,
                                       int k, float w[16]) {
#pragma unroll
    for (int i = 0; i < 16; i++) w[i] = W[(k + i) * HID + c];
}

// 16 k-steps: two broadcast LDS.128 per k (8 rows), weights in registers.
// kbase is a multiple of 16, so (k>>5) is constant across the chunk.
__device__ __forceinline__ void fma16(const float* __restrict__ act, int kbase,
                                      const float w[16], u64 acc[4]) {
    const float* base = act + kbase * 8 + ((kbase >> 5) << 2);
#pragma unroll
    for (int i = 0; i < 16; i++) {
        u64 ww;
        asm("mov.b64 %0, {%1, %1};" : "=l"(ww) : "f"(w[i]));
        const ulonglong2* a = (const ulonglong2*)(base + i * 8);
        ulonglong2 a01 = a[0];   // rows 0..3
        ulonglong2 a23 = a[1];   // rows 4..7
        acc[0] = fma2(a01.x, ww, acc[0]);
        acc[1] = fma2(a01.y, ww, acc[1]);
        acc[2] = fma2(a23.x, ww, acc[2]);
        acc[3] = fma2(a23.y, ww, acc[3]);
    }
}

__device__ __forceinline__ void unpack8(const u64 acc[4], float r[8]) {
#pragma unroll
    for (int j = 0; j < 4; j++)
        asm("mov.b64 {%0, %1}, %2;" : "=f"(r[2 * j]), "=f"(r[2 * j + 1]) : "l"(acc[j]));
}

__device__ __forceinline__ void red_xor(float r[8], int m) {
#pragma unroll
    for (int j = 0; j < 8; j++) r[j] += __shfl_xor_sync(0xffffffffu, r[j], m);
}

extern "C" __global__ void __launch_bounds__(NTHREADS, 1)
temporal_attn_fused(const float* __restrict__ h_prev,
                    const float* __restrict__ h_pred,
                    const float* __restrict__ Wv, const float* __restrict__ bv,
                    const float* __restrict__ Wo, const float* __restrict__ bo,
                    const float* __restrict__ gW1, const float* __restrict__ gb1,
                    const float* __restrict__ gW2, const float* __restrict__ gb2,
                    const float* __restrict__ mW1, const float* __restrict__ mb1,
                    const float* __restrict__ mW2, const float* __restrict__ mb2,
                    float* __restrict__ out) {
    __shared__ float sm[SMF_TOT];
    float* A  = sm + BUF_A;
    float* HV = sm + BUF_HV;
    float* C  = sm + BUF_C;
    float* G  = sm + BUF_G;

    const int tid = threadIdx.x;
    const int lane = tid & 31;
    const int wid = tid >> 5;
    const int s = lane & 3;                 // k-slice within warp
    const int c = wid * 8 + (lane >> 2);    // output column
    const int k0 = s * 32;
    const bool lead = (s == 0);
    const int r0 = blockIdx.x * ROWS;
    const int swc = SW(c);

    // Hoisted bias loads (off the post-barrier critical paths).
    const float bv_c = bv[c], bo_c = bo[c];
    const float gb1_c = gb1[c], gb2_c = gb2[c];
    const float mb1_c = mb1[c], mb2_c = mb2[c];

    float wpre[16], wt[16];
    load16(Wv, c, k0, wpre);                // S1 chunk0 in flight

    // Stage inputs, swizzled-transposed ([k][8 rows] + XOR pad).
#pragma unroll
    for (int j = 0; j < 2; j++) {
        int g = tid + j * NTHREADS;
        int r = g >> 7, cc = g & (HID - 1);
        int sw = SW(cc) + r;
        A[sw]  = h_pred[(r0 + r) * HID + cc];
        HV[sw] = h_prev[(r0 + r) * HID + cc];
    }
    __syncthreads();                         // bar0

    u64 acc[4];
    float rr[8], hcv[8];
#define GEMM_ZERO() { acc[0] = acc[1] = acc[2] = acc[3] = 0ULL; }

    // ---- S1: v = h_pred @ Wv + bv -> C ----
    GEMM_ZERO();
    fma16(A, k0, wpre, acc);
    load16(Wv, c, k0 + 16, wt);  fma16(A, k0 + 16, wt, acc);
    load16(gW1, c, k0, wpre);                // prefetch S3 chunk0
    unpack8(acc, rr); red_xor(rr, 1); red_xor(rr, 2);
    if (lead) {
#pragma unroll
        for (int r = 0; r < ROWS; r++) C[swc + r] = rr[r] + bv_c;
    }
    __syncthreads();                         // bar1

    // ---- S3: g1 = silu(h_pred@gW1_top + h_prev@gW1_bot + gb1) -> G ----
    GEMM_ZERO();
    fma16(A, k0, wpre, acc);
    load16(gW1, c, k0 + 16, wt);  fma16(A, k0 + 16, wt, acc);
    load16(gW1 + HID * HID, c, k0, wt);       fma16(HV, k0, wt, acc);
    load16(gW1 + HID * HID, c, k0 + 16, wt);  fma16(HV, k0 + 16, wt, acc);
    const float* Wm = (s < 2) ? Wo : gW2;     // merged-stage matrix (per-lane)
    const int k0m = (s & 1) * 64;             // merged-stage k-offset
    load16(Wm, c, k0m, wpre);                 // prefetch merged chunk0
    unpack8(acc, rr); red_xor(rr, 1); red_xor(rr, 2);
    if (lead) {
#pragma unroll
        for (int r = 0; r < ROWS; r++) {
            float x = rr[r] + gb1_c;
            G[swc + r] = x / (1.0f + __expf(-x));
        }
    }
    __syncthreads();                         // bar2

    // ---- S2+S4 merged: lanes s<2 do v@Wo, s>=2 do g1@gW2 (64 k each) ----
    {
        const float* actm = (s < 2) ? C : G;
        GEMM_ZERO();
        fma16(actm, k0m, wpre, acc);
        load16(Wm, c, k0m + 16, wt);  fma16(actm, k0m + 16, wt, acc);
        load16(Wm, c, k0m + 32, wt);  fma16(actm, k0m + 32, wt, acc);
        load16(Wm, c, k0m + 48, wt);  fma16(actm, k0m + 48, wt, acc);
        load16(mW1, c, k0, wpre);             // prefetch S5 chunk0
        unpack8(acc, rr);
        red_xor(rr, 1);                       // pairs (0,1)=S2, (2,3)=S4
        float x4[8];
#pragma unroll
        for (int j = 0; j < 8; j++) x4[j] = __shfl_xor_sync(0xffffffffu, rr[j], 2);
        if (lead) {
#pragma unroll
            for (int r = 0; r < ROWS; r++) {
                float outv = (float)NNODES * rr[r] + bo_c;
                float xg = x4[r] + gb2_c;
                float g = 1.0f / (1.0f + __expf(-xg));
                hcv[r] = HV[swc + r] + g * outv;
                A[swc + r] = hcv[r];          // h_corr (h_pred dead)
            }
        }
    }
    __syncthreads();                         // bar3

    // ---- S5: m1 = relu(h_corr@mW1_top + h_prev@mW1_bot + mb1) -> C ----
    GEMM_ZERO();
    fma16(A, k0, wpre, acc);
    load16(mW1, c, k0 + 16, wt);  fma16(A, k0 + 16, wt, acc);
    load16(mW1 + HID * HID, c, k0, wt);       fma16(HV, k0, wt, acc);
    load16(mW1 + HID * HID, c, k0 + 16, wt);  fma16(HV, k0 + 16, wt, acc);
    load16(mW2, c, k0, wpre);                 // prefetch S6 chunk0
    unpack8(acc, rr); red_xor(rr, 1); red_xor(rr, 2);
    if (lead) {
#pragma unroll
        for (int r = 0; r < ROWS; r++) C[swc + r] = fmaxf(rr[r] + mb1_c, 0.0f);
    }
    __syncthreads();                         // bar4

    // ---- S6: mixed = h_corr + m1 @ mW2 + mb2 -> G (plain layout) ----
    GEMM_ZERO();
    fma16(C, k0, wpre, acc);
    load16(mW2, c, k0 + 16, wt);  fma16(C, k0 + 16, wt, acc);
    unpack8(acc, rr); red_xor(rr, 1); red_xor(rr, 2);
    if (lead) {
#pragma unroll
        for (int r = 0; r < ROWS; r++) G[c * 8 + r] = hcv[r] + rr[r] + mb2_c;
    }
    __syncthreads();                         // bar5

    // Coalesced final store.
#pragma unroll
    for (int j = 0; j < 2; j++) {
        int g = tid + j * NTHREADS;
        int r = g >> 7, cc = g & (HID - 1);
        out[(r0 + r) * HID + cc] = G[cc * 8 + r];
    }
}

extern "C" void kernel_launch(void* const* d_in, const int* in_sizes, int n_in,
                              void* d_out, int out_size) {
    // metadata order: h_prev, h_pred, adj_rows, adj_cols, Wq, bq, Wk, bk,
    //                 Wv, bv, Wo, bo, gW1, gb1, gW2, gb2, mW1, mb1, mW2, mb2
    const float* h_prev = (const float*)d_in[0];
    const float* h_pred = (const float*)d_in[1];
    // d_in[2..7] (adjacency, Wq/bq/Wk/bk) are algebraically dead.
    const float* Wv  = (const float*)d_in[8];
    const float* bv  = (const float*)d_in[9];
    const float* Wo  = (const float*)d_in[10];
    const float* bo  = (const float*)d_in[11];
    const float* gW1 = (const float*)d_in[12];
    const float* gb1 = (const float*)d_in[13];
    const float* gW2 = (const float*)d_in[14];
    const float* gb2 = (const float*)d_in[15];
    const float* mW1 = (const float*)d_in[16];
    const float* mb1 = (const float*)d_in[17];
    const float* mW2 = (const float*)d_in[18];
    const float* mb2 = (const float*)d_in[19];
    float* out = (float*)d_out;

    temporal_attn_fused<<<NNODES / ROWS, NTHREADS>>>(
        h_prev, h_pred, Wv, bv, Wo, bo,
        gW1, gb1, gW2, gb2, mW1, mb1, mW2, mb2, out);
}

// round 10
// speedup vs baseline: 1.9336x; 1.9336x over previous
#include <cuda_runtime.h>
#include <cuda_bf16.h>
#include <math.h>

// Attention path collapses (softmax rows sum to 1; T,S fully contracted):
//   y = 1024 * (h_pred @ Wv + bv)
// Only Wv/Wo projection + gate MLP + mixer MLP survive.
//
// R9: R7 skeleton (512 thr / 4 k-slices, 1-line-per-LDG weight pattern,
// cross-barrier prefetch, regs=128) + R4's merged phase graph
// {S1,S3} -> {S2,S4} -> {S5} -> {S6}: 8 barriers instead of 11, dual 16KB
// partial buffers, 48KB static smem exactly (no attribute call).

#define HID 128
#define ROWS 8
#define SLICES 4
#define KS 32                    // k-values per slice
#define NNODES 1024
#define NTHREADS 512

typedef unsigned long long u64;

__device__ __forceinline__ u64 fma2(u64 a, u64 b, u64 c) {
    u64 d;
    asm("fma.rn.f32x2 %0, %1, %2, %3;" : "=l"(d) : "l"(a), "l"(b), "l"(c));
    return d;
}

__device__ __forceinline__ void load16(const float* __restrict__ W, int c,
                                       int k, float w[16]) {
#pragma unroll
    for (int i = 0; i < 16; i++) w[i] = W[(k + i) * HID + c];
}

// 16 k-steps: activations via two broadcast LDS.128 ([k][8 rows] fp32),
// weights already in registers.
__device__ __forceinline__ void fma16(const float* __restrict__ act, int k,
                                      const float w[16], u64 acc[4]) {
#pragma unroll
    for (int i = 0; i < 16; i++) {
        u64 ww;
        asm("mov.b64 %0, {%1, %1};" : "=l"(ww) : "f"(w[i]));
        const ulonglong2* a = (const ulonglong2*)(act + (k + i) * ROWS);
        ulonglong2 a01 = a[0];   // rows 0..3
        ulonglong2 a23 = a[1];   // rows 4..7
        acc[0] = fma2(a01.x, ww, acc[0]);
        acc[1] = fma2(a01.y, ww, acc[1]);
        acc[2] = fma2(a23.x, ww, acc[2]);
        acc[3] = fma2(a23.y, ww, acc[3]);
    }
}

__device__ __forceinline__ void part_store(float* dst, const u64 acc[4]) {
    ulonglong2* d = (ulonglong2*)dst;
    d[0] = make_ulonglong2(acc[0], acc[1]);
    d[1] = make_ulonglong2(acc[2], acc[3]);
}

extern "C" __global__ void __launch_bounds__(NTHREADS, 1)
temporal_attn_fused(const float* __restrict__ h_prev,
                    const float* __restrict__ h_pred,
                    const float* __restrict__ Wv, const float* __restrict__ bv,
                    const float* __restrict__ Wo, const float* __restrict__ bo,
                    const float* __restrict__ gW1, const float* __restrict__ gb1,
                    const float* __restrict__ gW2, const float* __restrict__ gb2,
                    const float* __restrict__ mW1, const float* __restrict__ mb1,
                    const float* __restrict__ mW2, const float* __restrict__ mb2,
                    float* __restrict__ out) {
    __shared__ float bufA[HID * ROWS];         // 4KB  h_pred, later h_corr
    __shared__ float hvF[HID * ROWS];          // 4KB  h_prev
    __shared__ float bufC[HID * ROWS];         // 4KB  v, later m1
    __shared__ float g1F[HID * ROWS];          // 4KB  gate hidden
    __shared__ float pA[SLICES * HID * ROWS];  // 16KB partials A
    __shared__ float pB[SLICES * HID * ROWS];  // 16KB partials B

    const int tid = threadIdx.x;
    const int c = tid & (HID - 1);   // output column (GEMM phase)
    const int s = tid >> 7;          // k-slice 0..3 (warp-uniform)
    const int k0 = s * KS;
    const int r0 = blockIdx.x * ROWS;
    const int p0 = tid, p1 = tid + NTHREADS;   // elements owned in reduces
    const int q0 = p0 >> 3, q1 = p1 >> 3;      // their column indices

    // Hoisted bias loads (off the post-barrier critical paths).
    const float bv0 = bv[q0], bv1 = bv[q1];
    const float bo0 = bo[q0], bo1 = bo[q1];
    const float gb10 = gb1[q0], gb11 = gb1[q1];
    const float gb20 = gb2[q0], gb21 = gb2[q1];
    const float mb10 = mb1[q0], mb11 = mb1[q1];
    const float mb20 = mb2[q0], mb21 = mb2[q1];

    float wpre[16], wt[16];
    load16(Wv, c, k0, wpre);         // P1 chunk0, in flight during staging

    // Stage input tiles transposed: [k][r], coalesced global reads.
#pragma unroll
    for (int j = 0; j < 2; j++) {
        int g = tid + j * NTHREADS;
        int r = g >> 7, cc = g & (HID - 1);
        bufA[cc * ROWS + r] = h_pred[(r0 + r) * HID + cc];
        hvF[cc * ROWS + r]  = h_prev[(r0 + r) * HID + cc];
    }
    __syncthreads();                              // bar0

    u64 acc[4];
    float* pAdst = pA + s * 1024 + c * ROWS;
    float* pBdst = pB + s * 1024 + c * ROWS;

#define GEMM_ZERO() { acc[0] = acc[1] = acc[2] = acc[3] = 0ULL; }
#define RED4A(x, p) float x = (pA[p] + pA[1024 + (p)]) + (pA[2048 + (p)] + pA[3072 + (p)])
#define RED4B(x, p) float x = (pB[p] + pB[1024 + (p)]) + (pB[2048 + (p)] + pB[3072 + (p)])

    float outv0, outv1, hcv0, hcv1;
    const float* Wm = (s < 2) ? Wo : gW2;      // P2 merged-stage matrix
    const int k0m = (s & 1) * 64;              // P2 merged-stage k-offset

    // ======== P1: S1 (v = hp@Wv) -> pA ; S3 (gate hidden pre-act) -> pB ====
    GEMM_ZERO();
    fma16(bufA, k0, wpre, acc);
    load16(Wv, c, k0 + 16, wt);  fma16(bufA, k0 + 16, wt, acc);
    load16(gW1, c, k0, wpre);                  // S3 chunk0
    part_store(pAdst, acc);
    GEMM_ZERO();
    fma16(bufA, k0, wpre, acc);
    load16(gW1, c, k0 + 16, wt);  fma16(bufA, k0 + 16, wt, acc);
    load16(gW1 + HID * HID, c, k0, wt);       fma16(hvF, k0, wt, acc);
    load16(gW1 + HID * HID, c, k0 + 16, wt);  fma16(hvF, k0 + 16, wt, acc);
    load16(Wm, c, k0m, wpre);                  // prefetch P2 chunk0
    part_store(pBdst, acc);
    __syncthreads();                              // bar1
    {
        RED4A(v0, p0); bufC[p0] = v0 + bv0;
        RED4A(v1, p1); bufC[p1] = v1 + bv1;
        RED4B(x0, p0); x0 += gb10; g1F[p0] = x0 / (1.0f + __expf(-x0));
        RED4B(x1, p1); x1 += gb11; g1F[p1] = x1 / (1.0f + __expf(-x1));
    }
    __syncthreads();                              // bar2

    // ======== P2: merged S2+S4 — slices 0-1: v@Wo, slices 2-3: g1@gW2 ======
    {
        const float* actm = (s < 2) ? bufC : g1F;
        GEMM_ZERO();
        fma16(actm, k0m, wpre, acc);
        load16(Wm, c, k0m + 16, wt);  fma16(actm, k0m + 16, wt, acc);
        load16(Wm, c, k0m + 32, wt);  fma16(actm, k0m + 32, wt, acc);
        load16(Wm, c, k0m + 48, wt);  fma16(actm, k0m + 48, wt, acc);
        load16(mW1, c, k0, wpre);              // prefetch P3 chunk0
        part_store(pAdst, acc);
    }
    __syncthreads();                              // bar3
    {
        float v0 = pA[p0] + pA[1024 + p0];           // S2 partials (slices 0-1)
        float v1 = pA[p1] + pA[1024 + p1];
        outv0 = (float)NNODES * v0 + bo0;
        outv1 = (float)NNODES * v1 + bo1;
        float x0 = pA[2048 + p0] + pA[3072 + p0];    // S4 partials (slices 2-3)
        float x1 = pA[2048 + p1] + pA[3072 + p1];
        x0 += gb20; x1 += gb21;
        float g0 = 1.0f / (1.0f + __expf(-x0));
        float g1 = 1.0f / (1.0f + __expf(-x1));
        hcv0 = hvF[p0] + g0 * outv0;
        hcv1 = hvF[p1] + g1 * outv1;
        bufA[p0] = hcv0;                             // h_corr (h_pred dead)
        bufA[p1] = hcv1;
    }
    __syncthreads();                              // bar4

    // ======== P3: S5 m1 = relu(hc@mW1_top + hv@mW1_bot + mb1) -> bufC ======
    GEMM_ZERO();
    fma16(bufA, k0, wpre, acc);
    load16(mW1, c, k0 + 16, wt);  fma16(bufA, k0 + 16, wt, acc);
    load16(mW1 + HID * HID, c, k0, wt);       fma16(hvF, k0, wt, acc);
    load16(mW1 + HID * HID, c, k0 + 16, wt);  fma16(hvF, k0 + 16, wt, acc);
    load16(mW2, c, k0, wpre);                  // prefetch P4 chunk0
    part_store(pAdst, acc);
    __syncthreads();                              // bar5
    {
        RED4A(x0, p0); bufC[p0] = fmaxf(x0 + mb10, 0.0f);
        RED4A(x1, p1); bufC[p1] = fmaxf(x1 + mb11, 0.0f);
    }
    __syncthreads();                              // bar6

    // ======== P4: S6 mixed = h_corr + m1@mW2 + mb2 -> global ========
    GEMM_ZERO();
    fma16(bufC, k0, wpre, acc);
    load16(mW2, c, k0 + 16, wt);  fma16(bufC, k0 + 16, wt, acc);
    part_store(pAdst, acc);
    __syncthreads();                              // bar7
    {
        RED4A(v0, p0);
        out[(r0 + (p0 & 7)) * HID + q0] = hcv0 + v0 + mb20;
        RED4A(v1, p1);
        out[(r0 + (p1 & 7)) * HID + q1] = hcv1 + v1 + mb21;
    }
}

extern "C" void kernel_launch(void* const* d_in, const int* in_sizes, int n_in,
                              void* d_out, int out_size) {
    // metadata order: h_prev, h_pred, adj_rows, adj_cols, Wq, bq, Wk, bk,
    //                 Wv, bv, Wo, bo, gW1, gb1, gW2, gb2, mW1, mb1, mW2, mb2
    const float* h_prev = (const float*)d_in[0];
    const float* h_pred = (const float*)d_in[1];
    // d_in[2..7] (adjacency, Wq/bq/Wk/bk) are algebraically dead.
    const float* Wv  = (const float*)d_in[8];
    const float* bv  = (const float*)d_in[9];
    const float* Wo  = (const float*)d_in[10];
    const float* bo  = (const float*)d_in[11];
    const float* gW1 = (const float*)d_in[12];
    const float* gb1 = (const float*)d_in[13];
    const float* gW2 = (const float*)d_in[14];
    const float* gb2 = (const float*)d_in[15];
    const float* mW1 = (const float*)d_in[16];
    const float* mb1 = (const float*)d_in[17];
    const float* mW2 = (const float*)d_in[18];
    const float* mb2 = (const float*)d_in[19];
    float* out = (float*)d_out;

    temporal_attn_fused<<<NNODES / ROWS, NTHREADS>>>(
        h_prev, h_pred, Wv, bv, Wo, bo,
        gW1, gb1, gW2, gb2, mW1, mb1, mW2, mb2, out);
}